// round 1
// baseline (speedup 1.0000x reference)
#include <cuda_runtime.h>
#include <cuda_bf16.h>
#include <math.h>

// ---------------------------------------------------------------------------
// Problem constants (fixed by the dataset)
// ---------------------------------------------------------------------------
#define NN      100000      // nodes
#define EE      1600000     // edges
#define F_IN    500
#define F_HID   256
#define F_OUT   40
#define K_STEPS 10

// ---------------------------------------------------------------------------
// Scratch (static __device__ globals; no allocations allowed)
// ---------------------------------------------------------------------------
__device__ float g_h1[(size_t)NN * F_HID];   // relu(x@w1+b1)        (~102 MB)
__device__ float g_ha[(size_t)NN * F_OUT];   // h_k ping             (16 MB)
__device__ float g_hb[(size_t)NN * F_OUT];   // h_k pong             (16 MB)
__device__ float g_hidden[(size_t)NN * F_OUT]; // accumulated output (16 MB)
__device__ float g_dinv[NN];
__device__ int   g_count[NN];
__device__ int   g_rowptr[NN + 1];
__device__ int   g_cur[NN];
__device__ int   g_csr_src[EE];
__device__ float g_csr_w[EE];

// ---------------------------------------------------------------------------
// CSR build
// ---------------------------------------------------------------------------
__global__ void zero_counts_kernel(int n) {
    int i = blockIdx.x * blockDim.x + threadIdx.x;
    if (i < n) g_count[i] = 0;
}

__global__ void count_kernel(const int* __restrict__ dst, int e) {
    int i = blockIdx.x * blockDim.x + threadIdx.x;
    if (i < e) atomicAdd(&g_count[dst[i]], 1);
}

// Single-block chunked inclusive scan -> exclusive rowptr, cursor copy, dinv.
__global__ void scan_kernel(int n, int e) {
    __shared__ int sh[1024];
    __shared__ int carry;
    if (threadIdx.x == 0) carry = 0;
    __syncthreads();
    for (int base = 0; base < n; base += 1024) {
        int i = base + (int)threadIdx.x;
        int v = (i < n) ? g_count[i] : 0;
        sh[threadIdx.x] = v;
        __syncthreads();
        #pragma unroll
        for (int off = 1; off < 1024; off <<= 1) {
            int t = (threadIdx.x >= (unsigned)off) ? sh[threadIdx.x - off] : 0;
            __syncthreads();
            sh[threadIdx.x] += t;
            __syncthreads();
        }
        int incl = sh[threadIdx.x];
        int excl = incl - v + carry;
        if (i < n) {
            g_rowptr[i] = excl;
            g_cur[i]    = excl;
            g_dinv[i]   = rsqrtf((float)v + 1.0f);  // +1 self loop
        }
        __syncthreads();
        if (threadIdx.x == 1023) carry += sh[1023];
        __syncthreads();
    }
    if (threadIdx.x == 0) g_rowptr[n] = e;
}

__global__ void fill_kernel(const int* __restrict__ src, const int* __restrict__ dst, int e) {
    int i = blockIdx.x * blockDim.x + threadIdx.x;
    if (i < e) {
        int s = src[i];
        int d = dst[i];
        int p = atomicAdd(&g_cur[d], 1);
        g_csr_src[p] = s;
        g_csr_w[p]   = g_dinv[s] * g_dinv[d];
    }
}

// ---------------------------------------------------------------------------
// GEMM1: h1 = relu(x @ w1 + b1)   [M,500] x [500,256]
// 128x128 block tile, BK=8, 256 threads, 8x8 microtile.
// ---------------------------------------------------------------------------
#define BM 128
#define BN 128
#define BK 8

__global__ void __launch_bounds__(256, 2)
gemm1_kernel(const float* __restrict__ A, const float* __restrict__ B,
             const float* __restrict__ bias, int M) {
    __shared__ float As[BK][BM];
    __shared__ float Bs[BK][BN];

    const int K = F_IN;   // 500
    const int N = F_HID;  // 256
    int tid  = threadIdx.x;
    int row0 = blockIdx.y * BM;
    int col0 = blockIdx.x * BN;

    // A: 128x8 = 1024 floats = 256 float4
    int a_row = tid >> 1;
    int a_k   = (tid & 1) * 4;
    // B: 8x128 = 1024 floats = 256 float4
    int b_k   = tid >> 5;
    int b_col = (tid & 31) * 4;

    int tx = tid & 15;       // col micro-block
    int ty = tid >> 4;       // row micro-block

    float acc[8][8];
    #pragma unroll
    for (int i = 0; i < 8; i++)
        #pragma unroll
        for (int j = 0; j < 8; j++) acc[i][j] = 0.f;

    for (int kt = 0; kt < K; kt += BK) {
        // Load A tile (transposed into smem)
        float4 av = make_float4(0.f, 0.f, 0.f, 0.f);
        int gr = row0 + a_row;
        int gk = kt + a_k;
        if (gr < M && gk < K)
            av = *(const float4*)(A + (size_t)gr * K + gk);
        As[a_k + 0][a_row] = av.x;
        As[a_k + 1][a_row] = av.y;
        As[a_k + 2][a_row] = av.z;
        As[a_k + 3][a_row] = av.w;

        // Load B tile
        float4 bv = make_float4(0.f, 0.f, 0.f, 0.f);
        int gkb = kt + b_k;
        if (gkb < K)
            bv = *(const float4*)(B + (size_t)gkb * N + col0 + b_col);
        *(float4*)(&Bs[b_k][b_col]) = bv;

        __syncthreads();

        #pragma unroll
        for (int k = 0; k < BK; ++k) {
            float a[8], b[8];
            #pragma unroll
            for (int i = 0; i < 8; i++) a[i] = As[k][ty * 8 + i];
            #pragma unroll
            for (int j = 0; j < 8; j++) b[j] = Bs[k][tx * 8 + j];
            #pragma unroll
            for (int i = 0; i < 8; i++)
                #pragma unroll
                for (int j = 0; j < 8; j++)
                    acc[i][j] += a[i] * b[j];
        }
        __syncthreads();
    }

    // Epilogue: bias + relu
    #pragma unroll
    for (int i = 0; i < 8; i++) {
        int r = row0 + ty * 8 + i;
        if (r >= M) continue;
        #pragma unroll
        for (int j = 0; j < 8; j += 4) {
            int c = col0 + tx * 8 + j;
            float4 v;
            v.x = fmaxf(acc[i][j + 0] + bias[c + 0], 0.f);
            v.y = fmaxf(acc[i][j + 1] + bias[c + 1], 0.f);
            v.z = fmaxf(acc[i][j + 2] + bias[c + 2], 0.f);
            v.w = fmaxf(acc[i][j + 3] + bias[c + 3], 0.f);
            *(float4*)(g_h1 + (size_t)r * N + c) = v;
        }
    }
}

// ---------------------------------------------------------------------------
// GEMM2 + init: h = h1 @ w2 + b2 ; hidden = temp[0] * h
// block: 256 threads = 8 col-groups (5 cols each) x 32 rows, 4 row-strips.
// ---------------------------------------------------------------------------
__global__ void __launch_bounds__(256)
gemm2_init_kernel(const float* __restrict__ w2, const float* __restrict__ b2,
                  const float* __restrict__ temp, int M) {
    __shared__ float w2s[F_HID * F_OUT];   // 256*40*4 = 40960 B
    __shared__ float b2s[F_OUT];

    int tid = threadIdx.x;
    for (int i = tid; i < F_HID * F_OUT; i += 256) w2s[i] = w2[i];
    if (tid < F_OUT) b2s[tid] = b2[tid];
    __syncthreads();

    int cx = tid & 7;    // col group -> cols cx*5 .. cx*5+4
    int ty = tid >> 3;   // 0..31
    int rbase = blockIdx.x * 128;

    float acc[4][5];
    #pragma unroll
    for (int i = 0; i < 4; i++)
        #pragma unroll
        for (int j = 0; j < 5; j++) acc[i][j] = 0.f;

    for (int k = 0; k < F_HID; ++k) {
        float a[4];
        #pragma unroll
        for (int i = 0; i < 4; i++) {
            int r = rbase + ty + 32 * i;
            a[i] = (r < M) ? g_h1[(size_t)r * F_HID + k] : 0.f;
        }
        #pragma unroll
        for (int j = 0; j < 5; j++) {
            float w = w2s[k * F_OUT + cx * 5 + j];
            #pragma unroll
            for (int i = 0; i < 4; i++) acc[i][j] += a[i] * w;
        }
    }

    float t0 = temp[0];
    #pragma unroll
    for (int i = 0; i < 4; i++) {
        int r = rbase + ty + 32 * i;
        if (r >= M) continue;
        #pragma unroll
        for (int j = 0; j < 5; j++) {
            int c = cx * 5 + j;
            float v = acc[i][j] + b2s[c];
            g_ha[(size_t)r * F_OUT + c]     = v;
            g_hidden[(size_t)r * F_OUT + c] = t0 * v;
        }
    }
}

// ---------------------------------------------------------------------------
// Propagation step: warp per dst node, lane l owns features l and 32+l (<40).
// h_out[d] = sum_e w[e]*h_in[src[e]] + dinv[d]^2 * h_in[d]
// hidden  += temp[k] * h_out
// ---------------------------------------------------------------------------
__global__ void __launch_bounds__(256)
prop_step_kernel(const float* __restrict__ temp, int n, int k, int odd) {
    int warp = (blockIdx.x * blockDim.x + threadIdx.x) >> 5;
    int lane = threadIdx.x & 31;
    if (warp >= n) return;
    int node = warp;

    const float* __restrict__ hin = odd ? g_ha : g_hb;
    float* __restrict__ hout      = odd ? g_hb : g_ha;

    int beg = g_rowptr[node];
    int end = g_rowptr[node + 1];

    float dv = g_dinv[node];
    float wself = dv * dv;

    const float* rin = hin + (size_t)node * F_OUT;
    float acc0 = wself * rin[lane];
    float acc1 = (lane < 8) ? wself * rin[32 + lane] : 0.f;

    for (int e = beg; e < end; e += 32) {
        int idx = e + lane;
        int s = 0;
        float w = 0.f;
        if (idx < end) {
            s = g_csr_src[idx];
            w = g_csr_w[idx];
        }
        int cnt = min(32, end - e);
        #pragma unroll 8
        for (int j = 0; j < cnt; ++j) {
            int   sj = __shfl_sync(0xffffffffu, s, j);
            float wj = __shfl_sync(0xffffffffu, w, j);
            const float* rs = hin + (size_t)sj * F_OUT;
            acc0 += wj * rs[lane];
            if (lane < 8) acc1 += wj * rs[32 + lane];
        }
    }

    float gamma = temp[k];
    size_t o = (size_t)node * F_OUT;
    hout[o + lane] = acc0;
    g_hidden[o + lane] += gamma * acc0;
    if (lane < 8) {
        hout[o + 32 + lane] = acc1;
        g_hidden[o + 32 + lane] += gamma * acc1;
    }
}

// ---------------------------------------------------------------------------
// log_softmax over 40 classes: warp per row.
// ---------------------------------------------------------------------------
__global__ void __launch_bounds__(256)
log_softmax_kernel(float* __restrict__ out, int n) {
    int warp = (blockIdx.x * blockDim.x + threadIdx.x) >> 5;
    int lane = threadIdx.x & 31;
    if (warp >= n) return;
    size_t o = (size_t)warp * F_OUT;

    float v0 = g_hidden[o + lane];
    float v1 = (lane < 8) ? g_hidden[o + 32 + lane] : -INFINITY;

    float m = fmaxf(v0, v1);
    #pragma unroll
    for (int off = 16; off; off >>= 1)
        m = fmaxf(m, __shfl_xor_sync(0xffffffffu, m, off));

    float s = expf(v0 - m) + ((lane < 8) ? expf(v1 - m) : 0.f);
    #pragma unroll
    for (int off = 16; off; off >>= 1)
        s += __shfl_xor_sync(0xffffffffu, s, off);

    float ls = logf(s);
    out[o + lane] = v0 - m - ls;
    if (lane < 8) out[o + 32 + lane] = v1 - m - ls;
}

// ---------------------------------------------------------------------------
// Launch
// ---------------------------------------------------------------------------
extern "C" void kernel_launch(void* const* d_in, const int* in_sizes, int n_in,
                              void* d_out, int out_size) {
    const float* x    = (const float*)d_in[0];
    const int*   ei   = (const int*)  d_in[1];
    const float* w1   = (const float*)d_in[2];
    const float* b1   = (const float*)d_in[3];
    const float* w2   = (const float*)d_in[4];
    const float* b2   = (const float*)d_in[5];
    const float* temp = (const float*)d_in[6];
    float* out = (float*)d_out;

    int N = in_sizes[0] / F_IN;   // 100000
    int E = in_sizes[1] / 2;      // 1600000
    const int* src = ei;
    const int* dst = ei + E;

    // CSR build
    zero_counts_kernel<<<(N + 255) / 256, 256>>>(N);
    count_kernel<<<(E + 255) / 256, 256>>>(dst, E);
    scan_kernel<<<1, 1024>>>(N, E);
    fill_kernel<<<(E + 255) / 256, 256>>>(src, dst, E);

    // MLP
    dim3 g1(F_HID / BN, (N + BM - 1) / BM);
    gemm1_kernel<<<g1, 256>>>(x, w1, b1, N);
    gemm2_init_kernel<<<(N + 127) / 128, 256>>>(w2, b2, temp, N);

    // APPNP-style propagation
    int warp_blocks = (N * 32 + 255) / 256;
    for (int k = 1; k <= K_STEPS; ++k)
        prop_step_kernel<<<warp_blocks, 256>>>(temp, N, k, k & 1);

    log_softmax_kernel<<<warp_blocks, 256>>>(out, N);
}

// round 2
// speedup vs baseline: 2.0390x; 2.0390x over previous
#include <cuda_runtime.h>
#include <cuda_bf16.h>
#include <math.h>
#include <stdint.h>

// ---------------------------------------------------------------------------
// Problem constants (fixed by the dataset)
// ---------------------------------------------------------------------------
#define NN      100000      // nodes
#define EE      1600000     // edges
#define F_IN    500
#define F_HID   256
#define F_OUT   40
#define K_STEPS 10

// ---------------------------------------------------------------------------
// Scratch (static __device__ globals; no allocations allowed)
// ---------------------------------------------------------------------------
__device__ float g_h1[(size_t)NN * F_HID];     // relu(x@w1+b1)      (~102 MB)
__device__ float g_ha[(size_t)NN * F_OUT];     // h_k ping           (16 MB)
__device__ float g_hb[(size_t)NN * F_OUT];     // h_k pong           (16 MB)
__device__ float g_hidden[(size_t)NN * F_OUT]; // accumulated output (16 MB)
__device__ float g_dinv[NN];
__device__ int   g_count[NN];
__device__ int   g_rowptr[NN + 1];
__device__ int   g_cur[NN];
__device__ int   g_bsum[128];
__device__ int   g_csr_src[EE];
__device__ float g_csr_w[EE];

// ---------------------------------------------------------------------------
// CSR build
// ---------------------------------------------------------------------------
__global__ void zero_counts_kernel(int n) {
    int i = blockIdx.x * blockDim.x + threadIdx.x;
    if (i < n) g_count[i] = 0;
}

__global__ void count_kernel(const int* __restrict__ dst, int e) {
    int i = blockIdx.x * blockDim.x + threadIdx.x;
    if (i < e) atomicAdd(&g_count[dst[i]], 1);
}

// Hierarchical scan, stage 1: per-block inclusive scan of 1024 counts.
__global__ void __launch_bounds__(1024)
scan1_kernel(int n) {
    __shared__ int sh[1024];
    int b = blockIdx.x;
    int tid = threadIdx.x;
    int i = b * 1024 + tid;
    int v = (i < n) ? g_count[i] : 0;
    sh[tid] = v;
    __syncthreads();
    #pragma unroll
    for (int off = 1; off < 1024; off <<= 1) {
        int t = (tid >= (unsigned)off) ? sh[tid - off] : 0;
        __syncthreads();
        sh[tid] += t;
        __syncthreads();
    }
    if (i < n) {
        g_rowptr[i] = sh[tid] - v;               // block-local exclusive
        g_dinv[i]   = rsqrtf((float)v + 1.0f);   // +1 self loop
    }
    if (tid == 1023) g_bsum[b] = sh[1023];
}

// Stage 2: exclusive scan of the (<=128) block sums.
__global__ void __launch_bounds__(128)
scan2_kernel(int nb) {
    __shared__ int sh[128];
    int tid = threadIdx.x;
    int v = (tid < nb) ? g_bsum[tid] : 0;
    sh[tid] = v;
    __syncthreads();
    #pragma unroll
    for (int off = 1; off < 128; off <<= 1) {
        int t = (tid >= (unsigned)off) ? sh[tid - off] : 0;
        __syncthreads();
        sh[tid] += t;
        __syncthreads();
    }
    if (tid < nb) g_bsum[tid] = sh[tid] - v;
}

// Stage 3: add block offsets, copy cursor, terminate rowptr.
__global__ void scan3_kernel(int n, int e) {
    int i = blockIdx.x * blockDim.x + threadIdx.x;
    if (i < n) {
        int rp = g_rowptr[i] + g_bsum[i >> 10];
        g_rowptr[i] = rp;
        g_cur[i]    = rp;
    }
    if (i == 0) g_rowptr[n] = e;
}

__global__ void fill_kernel(const int* __restrict__ src, const int* __restrict__ dst, int e) {
    int i = blockIdx.x * blockDim.x + threadIdx.x;
    if (i < e) {
        int s = src[i];
        int d = dst[i];
        int p = atomicAdd(&g_cur[d], 1);
        g_csr_src[p] = s;
        g_csr_w[p]   = g_dinv[s] * g_dinv[d];
    }
}

// ---------------------------------------------------------------------------
// GEMM1 (tensor cores): h1 = relu(x @ w1 + b1)   [M,500] x [500,256]
// mma.sync.m16n8k8 tf32, block tile 128x128x32, 8 warps (2 M x 4 N),
// warp tile 64x32. Inputs rounded to tf32 with cvt.rna at smem-store time.
// ---------------------------------------------------------------------------
__device__ __forceinline__ float to_tf32(float x) {
    uint32_t u;
    asm("cvt.rna.tf32.f32 %0, %1;" : "=r"(u) : "f"(x));
    return __uint_as_float(u);
}

__device__ __forceinline__ void mma_tf32(float c[4],
                                         const uint32_t a[4],
                                         const uint32_t b[2]) {
    asm volatile(
        "mma.sync.aligned.m16n8k8.row.col.f32.tf32.tf32.f32 "
        "{%0,%1,%2,%3}, {%4,%5,%6,%7}, {%8,%9}, {%0,%1,%2,%3};"
        : "+f"(c[0]), "+f"(c[1]), "+f"(c[2]), "+f"(c[3])
        : "r"(a[0]), "r"(a[1]), "r"(a[2]), "r"(a[3]), "r"(b[0]), "r"(b[1]));
}

__global__ void __launch_bounds__(256, 2)
gemm1_tc_kernel(const float* __restrict__ A, const float* __restrict__ B,
                const float* __restrict__ bias, int M) {
    __shared__ float As[128][36];   // conflict-free: bank = (4g + t) pattern
    __shared__ float Bs[32][136];   // conflict-free: bank = (8t + g) pattern

    const int K = F_IN;   // 500
    const int N = F_HID;  // 256
    int tid  = threadIdx.x;
    int warp = tid >> 5;
    int lane = tid & 31;
    int g = lane >> 2;    // 0..7
    int t = lane & 3;     // 0..3
    int wm = warp >> 2;   // 0..1 : row offset wm*64
    int wn = warp & 3;    // 0..3 : col offset wn*32
    int row0 = blockIdx.y * 128;
    int col0 = blockIdx.x * 128;

    float c[4][4][4];     // [mtile][ntile][frag]
    #pragma unroll
    for (int i = 0; i < 4; i++)
        #pragma unroll
        for (int j = 0; j < 4; j++)
            #pragma unroll
            for (int q = 0; q < 4; q++) c[i][j][q] = 0.f;

    int ar = tid >> 3;            // 0..31 (row within 32-strip)
    int ac = (tid & 7) * 4;       // 0..28
    int bkr = tid >> 3;           // 0..31 (k row of B tile)

    for (int kt = 0; kt < 512; kt += 32) {
        // --- stage A tile: 128 x 32 ---
        #pragma unroll
        for (int i = 0; i < 4; i++) {
            int r  = ar + 32 * i;
            int gr = row0 + r;
            int gk = kt + ac;
            float4 v = make_float4(0.f, 0.f, 0.f, 0.f);
            if (gr < M && gk < K)
                v = *(const float4*)(A + (size_t)gr * K + gk);
            float4 w;
            w.x = to_tf32(v.x); w.y = to_tf32(v.y);
            w.z = to_tf32(v.z); w.w = to_tf32(v.w);
            *(float4*)(&As[r][ac]) = w;
        }
        // --- stage B tile: 32 x 128 ---
        #pragma unroll
        for (int i = 0; i < 4; i++) {
            int col = ((tid & 7) + 8 * i) * 4;
            int gk  = kt + bkr;
            float4 v = make_float4(0.f, 0.f, 0.f, 0.f);
            if (gk < K)
                v = *(const float4*)(B + (size_t)gk * N + col0 + col);
            float4 w;
            w.x = to_tf32(v.x); w.y = to_tf32(v.y);
            w.z = to_tf32(v.z); w.w = to_tf32(v.w);
            *(float4*)(&Bs[bkr][col]) = w;
        }
        __syncthreads();

        #pragma unroll
        for (int ks = 0; ks < 4; ks++) {
            int k = ks * 8;
            uint32_t af[4][4], bf[4][2];
            #pragma unroll
            for (int mt = 0; mt < 4; mt++) {
                int rb = wm * 64 + mt * 16;
                af[mt][0] = __float_as_uint(As[rb + g    ][k + t    ]);
                af[mt][1] = __float_as_uint(As[rb + g + 8][k + t    ]);
                af[mt][2] = __float_as_uint(As[rb + g    ][k + t + 4]);
                af[mt][3] = __float_as_uint(As[rb + g + 8][k + t + 4]);
            }
            #pragma unroll
            for (int nt = 0; nt < 4; nt++) {
                int cb = wn * 32 + nt * 8 + g;
                bf[nt][0] = __float_as_uint(Bs[k + t    ][cb]);
                bf[nt][1] = __float_as_uint(Bs[k + t + 4][cb]);
            }
            #pragma unroll
            for (int mt = 0; mt < 4; mt++)
                #pragma unroll
                for (int nt = 0; nt < 4; nt++)
                    mma_tf32(c[mt][nt], af[mt], bf[nt]);
        }
        __syncthreads();
    }

    // Epilogue: bias + relu -> g_h1
    #pragma unroll
    for (int mt = 0; mt < 4; mt++) {
        #pragma unroll
        for (int nt = 0; nt < 4; nt++) {
            int cc = col0 + wn * 32 + nt * 8 + 2 * t;
            float b0 = bias[cc], b1 = bias[cc + 1];
            int r0 = row0 + wm * 64 + mt * 16 + g;
            if (r0 < M) {
                g_h1[(size_t)r0 * N + cc]     = fmaxf(c[mt][nt][0] + b0, 0.f);
                g_h1[(size_t)r0 * N + cc + 1] = fmaxf(c[mt][nt][1] + b1, 0.f);
            }
            int r1 = r0 + 8;
            if (r1 < M) {
                g_h1[(size_t)r1 * N + cc]     = fmaxf(c[mt][nt][2] + b0, 0.f);
                g_h1[(size_t)r1 * N + cc + 1] = fmaxf(c[mt][nt][3] + b1, 0.f);
            }
        }
    }
}

// ---------------------------------------------------------------------------
// GEMM2 + init: h = h1 @ w2 + b2 ; hidden = temp[0] * h
// 256 threads = 8 col-groups (5 cols) x 32 rows, 4 row-strips, float4 k-loop.
// ---------------------------------------------------------------------------
__global__ void __launch_bounds__(256)
gemm2_init_kernel(const float* __restrict__ w2, const float* __restrict__ b2,
                  const float* __restrict__ temp, int M) {
    __shared__ float w2s[F_HID * F_OUT];   // 40 KB
    __shared__ float b2s[F_OUT];

    int tid = threadIdx.x;
    for (int i = tid; i < F_HID * F_OUT; i += 256) w2s[i] = w2[i];
    if (tid < F_OUT) b2s[tid] = b2[tid];
    __syncthreads();

    int cx = tid & 7;    // col group -> cols cx*5 .. cx*5+4
    int ty = tid >> 3;   // 0..31
    int rbase = blockIdx.x * 128;

    float acc[4][5];
    #pragma unroll
    for (int i = 0; i < 4; i++)
        #pragma unroll
        for (int j = 0; j < 5; j++) acc[i][j] = 0.f;

    for (int k = 0; k < F_HID; k += 4) {
        float a[4][4];
        #pragma unroll
        for (int i = 0; i < 4; i++) {
            int r = rbase + ty + 32 * i;
            float4 v = make_float4(0.f, 0.f, 0.f, 0.f);
            if (r < M) v = *(const float4*)(g_h1 + (size_t)r * F_HID + k);
            a[i][0] = v.x; a[i][1] = v.y; a[i][2] = v.z; a[i][3] = v.w;
        }
        #pragma unroll
        for (int kk = 0; kk < 4; kk++) {
            #pragma unroll
            for (int j = 0; j < 5; j++) {
                float w = w2s[(k + kk) * F_OUT + cx * 5 + j];
                #pragma unroll
                for (int i = 0; i < 4; i++) acc[i][j] += a[i][kk] * w;
            }
        }
    }

    float t0 = temp[0];
    #pragma unroll
    for (int i = 0; i < 4; i++) {
        int r = rbase + ty + 32 * i;
        if (r >= M) continue;
        #pragma unroll
        for (int j = 0; j < 5; j++) {
            int c = cx * 5 + j;
            float v = acc[i][j] + b2s[c];
            g_ha[(size_t)r * F_OUT + c]     = v;
            g_hidden[(size_t)r * F_OUT + c] = t0 * v;
        }
    }
}

// ---------------------------------------------------------------------------
// Propagation step: warp per dst node, lane l owns features l and 32+l (<40).
// h_out[d] = sum_e w[e]*h_in[src[e]] + dinv[d]^2 * h_in[d]
// hidden  += temp[k] * h_out
// ---------------------------------------------------------------------------
__global__ void __launch_bounds__(256)
prop_step_kernel(const float* __restrict__ temp, int n, int k, int odd) {
    int warp = (blockIdx.x * blockDim.x + threadIdx.x) >> 5;
    int lane = threadIdx.x & 31;
    if (warp >= n) return;
    int node = warp;

    const float* __restrict__ hin = odd ? g_ha : g_hb;
    float* __restrict__ hout      = odd ? g_hb : g_ha;

    int beg = g_rowptr[node];
    int end = g_rowptr[node + 1];

    float dv = g_dinv[node];
    float wself = dv * dv;

    const float* rin = hin + (size_t)node * F_OUT;
    float acc0 = wself * rin[lane];
    float acc1 = (lane < 8) ? wself * rin[32 + lane] : 0.f;

    for (int e = beg; e < end; e += 32) {
        int idx = e + lane;
        int s = 0;
        float w = 0.f;
        if (idx < end) {
            s = g_csr_src[idx];
            w = g_csr_w[idx];
        }
        int cnt = min(32, end - e);
        #pragma unroll 8
        for (int j = 0; j < cnt; ++j) {
            int   sj = __shfl_sync(0xffffffffu, s, j);
            float wj = __shfl_sync(0xffffffffu, w, j);
            const float* rs = hin + (size_t)sj * F_OUT;
            acc0 += wj * rs[lane];
            if (lane < 8) acc1 += wj * rs[32 + lane];
        }
    }

    float gamma = temp[k];
    size_t o = (size_t)node * F_OUT;
    hout[o + lane] = acc0;
    g_hidden[o + lane] += gamma * acc0;
    if (lane < 8) {
        hout[o + 32 + lane] = acc1;
        g_hidden[o + 32 + lane] += gamma * acc1;
    }
}

// ---------------------------------------------------------------------------
// log_softmax over 40 classes: warp per row.
// ---------------------------------------------------------------------------
__global__ void __launch_bounds__(256)
log_softmax_kernel(float* __restrict__ out, int n) {
    int warp = (blockIdx.x * blockDim.x + threadIdx.x) >> 5;
    int lane = threadIdx.x & 31;
    if (warp >= n) return;
    size_t o = (size_t)warp * F_OUT;

    float v0 = g_hidden[o + lane];
    float v1 = (lane < 8) ? g_hidden[o + 32 + lane] : -INFINITY;

    float m = fmaxf(v0, v1);
    #pragma unroll
    for (int off = 16; off; off >>= 1)
        m = fmaxf(m, __shfl_xor_sync(0xffffffffu, m, off));

    float s = expf(v0 - m) + ((lane < 8) ? expf(v1 - m) : 0.f);
    #pragma unroll
    for (int off = 16; off; off >>= 1)
        s += __shfl_xor_sync(0xffffffffu, s, off);

    float ls = logf(s);
    out[o + lane] = v0 - m - ls;
    if (lane < 8) out[o + 32 + lane] = v1 - m - ls;
}

// ---------------------------------------------------------------------------
// Launch
// ---------------------------------------------------------------------------
extern "C" void kernel_launch(void* const* d_in, const int* in_sizes, int n_in,
                              void* d_out, int out_size) {
    const float* x    = (const float*)d_in[0];
    const int*   ei   = (const int*)  d_in[1];
    const float* w1   = (const float*)d_in[2];
    const float* b1   = (const float*)d_in[3];
    const float* w2   = (const float*)d_in[4];
    const float* b2   = (const float*)d_in[5];
    const float* temp = (const float*)d_in[6];
    float* out = (float*)d_out;

    int N = in_sizes[0] / F_IN;   // 100000
    int E = in_sizes[1] / 2;      // 1600000
    const int* src = ei;
    const int* dst = ei + E;

    // CSR build
    zero_counts_kernel<<<(N + 255) / 256, 256>>>(N);
    count_kernel<<<(E + 255) / 256, 256>>>(dst, E);
    int nb = (N + 1023) / 1024;
    scan1_kernel<<<nb, 1024>>>(N);
    scan2_kernel<<<1, 128>>>(nb);
    scan3_kernel<<<(N + 255) / 256, 256>>>(N, E);
    fill_kernel<<<(E + 255) / 256, 256>>>(src, dst, E);

    // MLP
    dim3 g1(F_HID / 128, (N + 127) / 128);
    gemm1_tc_kernel<<<g1, 256>>>(x, w1, b1, N);
    gemm2_init_kernel<<<(N + 127) / 128, 256>>>(w2, b2, temp, N);

    // APPNP-style propagation
    int warp_blocks = (N * 32 + 255) / 256;
    for (int k = 1; k <= K_STEPS; ++k)
        prop_step_kernel<<<warp_blocks, 256>>>(temp, N, k, k & 1);

    log_softmax_kernel<<<warp_blocks, 256>>>(out, N);
}

// round 3
// speedup vs baseline: 2.0535x; 1.0072x over previous
#include <cuda_runtime.h>
#include <cuda_bf16.h>
#include <math.h>
#include <stdint.h>

// ---------------------------------------------------------------------------
// Problem constants (fixed by the dataset)
// ---------------------------------------------------------------------------
#define NN      100000      // nodes
#define EE      1600000     // edges
#define F_IN    500
#define F_HID   256
#define F_OUT   40
#define K_STEPS 10

// ---------------------------------------------------------------------------
// Scratch (static __device__ globals; no allocations allowed)
// ---------------------------------------------------------------------------
__device__ float g_h1[(size_t)NN * F_HID];     // relu(x@w1+b1)      (~102 MB)
__device__ float g_ha[(size_t)NN * F_OUT];     // h_k ping           (16 MB)
__device__ float g_hb[(size_t)NN * F_OUT];     // h_k pong           (16 MB)
__device__ float g_hidden[(size_t)NN * F_OUT]; // accumulated output (16 MB)
__device__ float g_w1t[F_IN * F_HID];          // w1 pre-rounded to tf32
__device__ float g_dinv[NN];
__device__ int   g_count[NN];
__device__ int   g_rowptr[NN + 1];
__device__ int   g_cur[NN];
__device__ int   g_bsum[128];
__device__ int2  g_csr[EE];                    // packed {src, w bits}

// ---------------------------------------------------------------------------
// CSR build
// ---------------------------------------------------------------------------
__global__ void count_kernel(const int* __restrict__ dst, int e) {
    int i = blockIdx.x * blockDim.x + threadIdx.x;
    if (i < e) atomicAdd(&g_count[dst[i]], 1);
}

__global__ void __launch_bounds__(1024)
scan1_kernel(int n) {
    __shared__ int sh[1024];
    int b = blockIdx.x;
    int tid = threadIdx.x;
    int i = b * 1024 + tid;
    int v = (i < n) ? g_count[i] : 0;
    sh[tid] = v;
    __syncthreads();
    #pragma unroll
    for (int off = 1; off < 1024; off <<= 1) {
        int t = (tid >= (unsigned)off) ? sh[tid - off] : 0;
        __syncthreads();
        sh[tid] += t;
        __syncthreads();
    }
    if (i < n) {
        g_rowptr[i] = sh[tid] - v;               // block-local exclusive
        g_dinv[i]   = rsqrtf((float)v + 1.0f);   // +1 self loop
    }
    if (tid == 1023) g_bsum[b] = sh[1023];
}

__global__ void __launch_bounds__(128)
scan2_kernel(int nb) {
    __shared__ int sh[128];
    int tid = threadIdx.x;
    int v = (tid < nb) ? g_bsum[tid] : 0;
    sh[tid] = v;
    __syncthreads();
    #pragma unroll
    for (int off = 1; off < 128; off <<= 1) {
        int t = (tid >= (unsigned)off) ? sh[tid - off] : 0;
        __syncthreads();
        sh[tid] += t;
        __syncthreads();
    }
    if (tid < nb) g_bsum[tid] = sh[tid] - v;
}

__global__ void scan3_kernel(int n, int e) {
    int i = blockIdx.x * blockDim.x + threadIdx.x;
    if (i < n) {
        int rp = g_rowptr[i] + g_bsum[i >> 10];
        g_rowptr[i] = rp;
        g_cur[i]    = rp;
    }
    if (i == 0) g_rowptr[n] = e;
}

__global__ void fill_kernel(const int* __restrict__ src, const int* __restrict__ dst, int e) {
    int i = blockIdx.x * blockDim.x + threadIdx.x;
    if (i < e) {
        int s = src[i];
        int d = dst[i];
        int p = atomicAdd(&g_cur[d], 1);
        g_csr[p] = make_int2(s, __float_as_int(g_dinv[s] * g_dinv[d]));
    }
}

// ---------------------------------------------------------------------------
// tf32 helpers
// ---------------------------------------------------------------------------
__device__ __forceinline__ float to_tf32(float x) {
    uint32_t u;
    asm("cvt.rna.tf32.f32 %0, %1;" : "=r"(u) : "f"(x));
    return __uint_as_float(u);
}

__global__ void w1cvt_kernel(const float* __restrict__ w1, int n) {
    int i = blockIdx.x * blockDim.x + threadIdx.x;
    if (i < n) g_w1t[i] = to_tf32(w1[i]);
}

__device__ __forceinline__ void mma_tf32(float c[4],
                                         const uint32_t a[4],
                                         const uint32_t b[2]) {
    asm volatile(
        "mma.sync.aligned.m16n8k8.row.col.f32.tf32.tf32.f32 "
        "{%0,%1,%2,%3}, {%4,%5,%6,%7}, {%8,%9}, {%0,%1,%2,%3};"
        : "+f"(c[0]), "+f"(c[1]), "+f"(c[2]), "+f"(c[3])
        : "r"(a[0]), "r"(a[1]), "r"(a[2]), "r"(a[3]), "r"(b[0]), "r"(b[1]));
}

__device__ __forceinline__ void cp_async16(uint32_t dst_smem, const void* src, int src_bytes) {
    asm volatile("cp.async.cg.shared.global [%0], [%1], 16, %2;\n"
                 :: "r"(dst_smem), "l"(src), "r"(src_bytes));
}
__device__ __forceinline__ void cp_commit() {
    asm volatile("cp.async.commit_group;\n");
}

// ---------------------------------------------------------------------------
// GEMM1 (tensor cores): h1 = relu(x @ w1 + b1)   [M,500] x [500,256]
// 128x128x32 block tile, 4 warps (2x2) of 64x64 warp tiles,
// 2-stage cp.async double buffer. B (w1) pre-rounded to tf32.
// ---------------------------------------------------------------------------
#define G1_APAD 36
#define G1_BPAD 132
#define G1_ASZ  (128 * G1_APAD)          // floats per stage
#define G1_BSZ  (32 * G1_BPAD)
#define G1_SMEM ((2 * (G1_ASZ + G1_BSZ)) * 4)   // bytes

__global__ void __launch_bounds__(128, 2)
gemm1_tc_kernel(const float* __restrict__ A, const float* __restrict__ bias, int M) {
    extern __shared__ float sm[];
    float* As = sm;                         // [2][128][36]
    float* Bs = sm + 2 * G1_ASZ;            // [2][32][132]

    const int K = F_IN;   // 500
    const int N = F_HID;  // 256
    const int NT = 16;    // 512 / 32 k-tiles

    int tid  = threadIdx.x;
    int warp = tid >> 5;
    int lane = tid & 31;
    int g = lane >> 2;    // 0..7
    int t = lane & 3;     // 0..3
    int wm = warp >> 1;   // 0..1 : row offset wm*64
    int wn = warp & 1;    // 0..1 : col offset wn*64
    int row0 = blockIdx.y * 128;
    int col0 = blockIdx.x * 128;

    // staging coords
    int ar = tid >> 3;            // 0..15
    int ac = (tid & 7) * 4;       // 0..28
    int br = tid >> 5;            // 0..3
    int bc = (tid & 31) * 4;      // 0..124

    uint32_t as_base = (uint32_t)__cvta_generic_to_shared(As);
    uint32_t bs_base = (uint32_t)__cvta_generic_to_shared(Bs);

    float c[4][8][4];
    #pragma unroll
    for (int i = 0; i < 4; i++)
        #pragma unroll
        for (int j = 0; j < 8; j++)
            #pragma unroll
            for (int q = 0; q < 4; q++) c[i][j][q] = 0.f;

    const float4 z4 = make_float4(0.f, 0.f, 0.f, 0.f);

    // ---- stage tile `tt` into buffer b ----
    auto stage = [&](int tt, int b) {
        int kt = tt * 32;
        float* Asb = As + b * G1_ASZ;
        float* Bsb = Bs + b * G1_BSZ;
        #pragma unroll
        for (int i = 0; i < 8; i++) {
            int r  = ar + 16 * i;
            int gr = row0 + r;
            int gk = kt + ac;
            float* dst = Asb + r * G1_APAD + ac;
            if (gr < M && gk < K) {
                int bytes = (K - gk) * 4;
                bytes = bytes > 16 ? 16 : bytes;
                cp_async16(as_base + (uint32_t)((dst - As) * 4),
                           A + (size_t)gr * K + gk, bytes);
            } else {
                *(float4*)dst = z4;
            }
        }
        #pragma unroll
        for (int i = 0; i < 8; i++) {
            int r  = br + 4 * i;
            int gk = kt + r;
            float* dst = Bsb + r * G1_BPAD + bc;
            if (gk < K) {
                cp_async16(bs_base + (uint32_t)((dst - Bs) * 4),
                           g_w1t + (size_t)gk * N + col0 + bc, 16);
            } else {
                *(float4*)dst = z4;
            }
        }
        cp_commit();
    };

    stage(0, 0);

    for (int tt = 0; tt < NT; ++tt) {
        if (tt + 1 < NT) {
            stage(tt + 1, (tt + 1) & 1);
            asm volatile("cp.async.wait_group 1;\n");
        } else {
            asm volatile("cp.async.wait_group 0;\n");
        }
        __syncthreads();

        const float* Asb = As + (tt & 1) * G1_ASZ;
        const float* Bsb = Bs + (tt & 1) * G1_BSZ;

        #pragma unroll
        for (int ks = 0; ks < 4; ks++) {
            int k = ks * 8;
            // B fragments (already tf32-rounded)
            uint32_t bf[8][2];
            #pragma unroll
            for (int nt = 0; nt < 8; nt++) {
                int cb = wn * 64 + nt * 8 + g;
                bf[nt][0] = __float_as_uint(Bsb[(k + t)     * G1_BPAD + cb]);
                bf[nt][1] = __float_as_uint(Bsb[(k + t + 4) * G1_BPAD + cb]);
            }
            #pragma unroll
            for (int mt = 0; mt < 4; mt++) {
                int rb = wm * 64 + mt * 16;
                uint32_t af[4];
                af[0] = __float_as_uint(to_tf32(Asb[(rb + g)     * G1_APAD + k + t]));
                af[1] = __float_as_uint(to_tf32(Asb[(rb + g + 8) * G1_APAD + k + t]));
                af[2] = __float_as_uint(to_tf32(Asb[(rb + g)     * G1_APAD + k + t + 4]));
                af[3] = __float_as_uint(to_tf32(Asb[(rb + g + 8) * G1_APAD + k + t + 4]));
                #pragma unroll
                for (int nt = 0; nt < 8; nt++)
                    mma_tf32(c[mt][nt], af, bf[nt]);
            }
        }
        __syncthreads();
    }

    // Epilogue: bias + relu -> g_h1 (streaming stores)
    #pragma unroll
    for (int nt = 0; nt < 8; nt++) {
        int cc = col0 + wn * 64 + nt * 8 + 2 * t;
        float b0 = bias[cc], b1 = bias[cc + 1];
        #pragma unroll
        for (int mt = 0; mt < 4; mt++) {
            int r0 = row0 + wm * 64 + mt * 16 + g;
            if (r0 < M) {
                float2 v0 = make_float2(fmaxf(c[mt][nt][0] + b0, 0.f),
                                        fmaxf(c[mt][nt][1] + b1, 0.f));
                __stcs((float2*)(g_h1 + (size_t)r0 * N + cc), v0);
            }
            int r1 = r0 + 8;
            if (r1 < M) {
                float2 v1 = make_float2(fmaxf(c[mt][nt][2] + b0, 0.f),
                                        fmaxf(c[mt][nt][3] + b1, 0.f));
                __stcs((float2*)(g_h1 + (size_t)r1 * N + cc), v1);
            }
        }
    }
}

// ---------------------------------------------------------------------------
// GEMM2 + init: h = h1 @ w2 + b2 ; hidden = temp[0] * h
// ---------------------------------------------------------------------------
__global__ void __launch_bounds__(256)
gemm2_init_kernel(const float* __restrict__ w2, const float* __restrict__ b2,
                  const float* __restrict__ temp, int M) {
    __shared__ float w2s[F_HID * F_OUT];   // 40 KB
    __shared__ float b2s[F_OUT];

    int tid = threadIdx.x;
    for (int i = tid; i < F_HID * F_OUT; i += 256) w2s[i] = w2[i];
    if (tid < F_OUT) b2s[tid] = b2[tid];
    __syncthreads();

    int cx = tid & 7;    // col group -> cols cx*5 .. cx*5+4
    int ty = tid >> 3;   // 0..31
    int rbase = blockIdx.x * 128;

    float acc[4][5];
    #pragma unroll
    for (int i = 0; i < 4; i++)
        #pragma unroll
        for (int j = 0; j < 5; j++) acc[i][j] = 0.f;

    for (int k = 0; k < F_HID; k += 4) {
        float a[4][4];
        #pragma unroll
        for (int i = 0; i < 4; i++) {
            int r = rbase + ty + 32 * i;
            float4 v = make_float4(0.f, 0.f, 0.f, 0.f);
            if (r < M) v = __ldcs((const float4*)(g_h1 + (size_t)r * F_HID + k));
            a[i][0] = v.x; a[i][1] = v.y; a[i][2] = v.z; a[i][3] = v.w;
        }
        #pragma unroll
        for (int kk = 0; kk < 4; kk++) {
            #pragma unroll
            for (int j = 0; j < 5; j++) {
                float w = w2s[(k + kk) * F_OUT + cx * 5 + j];
                #pragma unroll
                for (int i = 0; i < 4; i++) acc[i][j] += a[i][kk] * w;
            }
        }
    }

    float t0 = temp[0];
    #pragma unroll
    for (int i = 0; i < 4; i++) {
        int r = rbase + ty + 32 * i;
        if (r >= M) continue;
        #pragma unroll
        for (int j = 0; j < 5; j++) {
            int c = cx * 5 + j;
            float v = acc[i][j] + b2s[c];
            g_ha[(size_t)r * F_OUT + c]     = v;
            g_hidden[(size_t)r * F_OUT + c] = t0 * v;
        }
    }
}

// ---------------------------------------------------------------------------
// Propagation: warp per dst node, lane l owns features l and 32+l (<40).
// h_out[d] = sum_e w[e]*h_in[src[e]] + dinv[d]^2 * h_in[d]
// ---------------------------------------------------------------------------
__device__ __forceinline__ void prop_accum(int node, const float* __restrict__ hin,
                                           int lane, float& acc0, float& acc1) {
    int beg = g_rowptr[node];
    int end = g_rowptr[node + 1];

    float dv = g_dinv[node];
    float wself = dv * dv;

    const float* rin = hin + (size_t)node * F_OUT;
    acc0 = wself * rin[lane];
    acc1 = (lane < 8) ? wself * rin[32 + lane] : 0.f;

    for (int e = beg; e < end; e += 32) {
        int idx = e + lane;
        int2 ev = make_int2(0, 0);
        if (idx < end) ev = g_csr[idx];
        int cnt = min(32, end - e);
        #pragma unroll 8
        for (int j = 0; j < cnt; ++j) {
            int   sj = __shfl_sync(0xffffffffu, ev.x, j);
            float wj = __int_as_float(__shfl_sync(0xffffffffu, ev.y, j));
            const float* rs = hin + (size_t)sj * F_OUT;
            acc0 += wj * rs[lane];
            if (lane < 8) acc1 += wj * rs[32 + lane];
        }
    }
}

__global__ void __launch_bounds__(256)
prop_step_kernel(const float* __restrict__ temp, int n, int k, int odd) {
    int warp = (blockIdx.x * blockDim.x + threadIdx.x) >> 5;
    int lane = threadIdx.x & 31;
    if (warp >= n) return;

    const float* __restrict__ hin = odd ? g_ha : g_hb;
    float* __restrict__ hout      = odd ? g_hb : g_ha;

    float acc0, acc1;
    prop_accum(warp, hin, lane, acc0, acc1);

    float gamma = temp[k];
    size_t o = (size_t)warp * F_OUT;
    hout[o + lane] = acc0;
    g_hidden[o + lane] += gamma * acc0;
    if (lane < 8) {
        hout[o + 32 + lane] = acc1;
        g_hidden[o + 32 + lane] += gamma * acc1;
    }
}

// Final step (k = K_STEPS, hin = g_hb) fused with log_softmax -> out.
__global__ void __launch_bounds__(256)
prop_last_kernel(const float* __restrict__ temp, int n, float* __restrict__ out) {
    int warp = (blockIdx.x * blockDim.x + threadIdx.x) >> 5;
    int lane = threadIdx.x & 31;
    if (warp >= n) return;

    float acc0, acc1;
    prop_accum(warp, g_hb, lane, acc0, acc1);

    float gamma = temp[K_STEPS];
    size_t o = (size_t)warp * F_OUT;
    float v0 = g_hidden[o + lane] + gamma * acc0;
    float v1 = (lane < 8) ? (g_hidden[o + 32 + lane] + gamma * acc1) : -INFINITY;

    float m = fmaxf(v0, v1);
    #pragma unroll
    for (int off = 16; off; off >>= 1)
        m = fmaxf(m, __shfl_xor_sync(0xffffffffu, m, off));

    float s = expf(v0 - m) + ((lane < 8) ? expf(v1 - m) : 0.f);
    #pragma unroll
    for (int off = 16; off; off >>= 1)
        s += __shfl_xor_sync(0xffffffffu, s, off);

    float ls = logf(s);
    out[o + lane] = v0 - m - ls;
    if (lane < 8) out[o + 32 + lane] = v1 - m - ls;
}

// ---------------------------------------------------------------------------
// Launch
// ---------------------------------------------------------------------------
extern "C" void kernel_launch(void* const* d_in, const int* in_sizes, int n_in,
                              void* d_out, int out_size) {
    const float* x    = (const float*)d_in[0];
    const int*   ei   = (const int*)  d_in[1];
    const float* w1   = (const float*)d_in[2];
    const float* b1   = (const float*)d_in[3];
    const float* w2   = (const float*)d_in[4];
    const float* b2   = (const float*)d_in[5];
    const float* temp = (const float*)d_in[6];
    float* out = (float*)d_out;

    int N = in_sizes[0] / F_IN;   // 100000
    int E = in_sizes[1] / 2;      // 1600000
    const int* src = ei;
    const int* dst = ei + E;

    // CSR build
    void* count_ptr = nullptr;
    cudaGetSymbolAddress(&count_ptr, g_count);
    cudaMemsetAsync(count_ptr, 0, (size_t)N * sizeof(int));
    count_kernel<<<(E + 255) / 256, 256>>>(dst, E);
    int nb = (N + 1023) / 1024;
    scan1_kernel<<<nb, 1024>>>(N);
    scan2_kernel<<<1, 128>>>(nb);
    scan3_kernel<<<(N + 255) / 256, 256>>>(N, E);
    fill_kernel<<<(E + 255) / 256, 256>>>(src, dst, E);

    // MLP
    w1cvt_kernel<<<(F_IN * F_HID + 255) / 256, 256>>>(w1, F_IN * F_HID);
    cudaFuncSetAttribute(gemm1_tc_kernel,
                         cudaFuncAttributeMaxDynamicSharedMemorySize, G1_SMEM);
    dim3 g1(F_HID / 128, (N + 127) / 128);
    gemm1_tc_kernel<<<g1, 128, G1_SMEM>>>(x, b1, N);
    gemm2_init_kernel<<<(N + 127) / 128, 256>>>(w2, b2, temp, N);

    // APPNP-style propagation (last step fused with log_softmax)
    int warp_blocks = (N * 32 + 255) / 256;
    for (int k = 1; k < K_STEPS; ++k)
        prop_step_kernel<<<warp_blocks, 256>>>(temp, N, k, k & 1);
    prop_last_kernel<<<warp_blocks, 256>>>(temp, N, out);
}

// round 6
// speedup vs baseline: 2.1270x; 1.0358x over previous
#include <cuda_runtime.h>
#include <cuda_bf16.h>
#include <math.h>
#include <stdint.h>

// ---------------------------------------------------------------------------
// Problem constants (fixed by the dataset)
// ---------------------------------------------------------------------------
#define NN      100000      // nodes
#define NN_PAD  100096      // padded to 128-row multiple
#define EE      1600000     // edges
#define F_IN    500
#define F_HID   256
#define F_OUT   40
#define F_PAD   64          // padded feature row for prop buffers (256B lines)
#define K_STEPS 10

// ---------------------------------------------------------------------------
// Scratch (static __device__ globals; no allocations allowed)
// ---------------------------------------------------------------------------
__device__ __nv_bfloat16 g_h1b[(size_t)NN_PAD * F_HID];  // relu(x@w1+b1), bf16 (51MB)
__device__ __nv_bfloat16 g_w1b[256 * 512];               // w1^T bf16 [n][k], k zero-padded
__device__ __nv_bfloat16 g_w2b[40 * 256];                // w2^T bf16 [n][k]
__device__ float g_ha[(size_t)NN_PAD * F_PAD];           // h_k ping (25.6MB)
__device__ float g_hb[(size_t)NN_PAD * F_PAD];           // h_k pong
__device__ float g_hidden[(size_t)NN_PAD * F_OUT];       // accumulator (16MB)
__device__ float g_dinv[NN];
__device__ int   g_count[NN];
__device__ int   g_rowptr[NN + 1];
__device__ int   g_cur[NN];
__device__ int   g_bsum[128];
__device__ int2  g_csr[EE];                              // packed {src, w bits}

// ---------------------------------------------------------------------------
// CSR build
// ---------------------------------------------------------------------------
__global__ void count_kernel(const int* __restrict__ dst, int e) {
    int i = blockIdx.x * blockDim.x + threadIdx.x;
    if (i < e) atomicAdd(&g_count[dst[i]], 1);
}

__global__ void __launch_bounds__(1024)
scan1_kernel(int n) {
    __shared__ int sh[1024];
    int b = blockIdx.x;
    int tid = threadIdx.x;
    int i = b * 1024 + tid;
    int v = (i < n) ? g_count[i] : 0;
    sh[tid] = v;
    __syncthreads();
    #pragma unroll
    for (int off = 1; off < 1024; off <<= 1) {
        int t = (tid >= (unsigned)off) ? sh[tid - off] : 0;
        __syncthreads();
        sh[tid] += t;
        __syncthreads();
    }
    if (i < n) {
        g_rowptr[i] = sh[tid] - v;               // block-local exclusive
        g_dinv[i]   = rsqrtf((float)v + 1.0f);   // +1 self loop
    }
    if (tid == 1023) g_bsum[b] = sh[1023];
}

__global__ void __launch_bounds__(128)
scan2_kernel(int nb) {
    __shared__ int sh[128];
    int tid = threadIdx.x;
    int v = (tid < nb) ? g_bsum[tid] : 0;
    sh[tid] = v;
    __syncthreads();
    #pragma unroll
    for (int off = 1; off < 128; off <<= 1) {
        int t = (tid >= (unsigned)off) ? sh[tid - off] : 0;
        __syncthreads();
        sh[tid] += t;
        __syncthreads();
    }
    if (tid < nb) g_bsum[tid] = sh[tid] - v;
}

__global__ void scan3_kernel(int n, int e) {
    int i = blockIdx.x * blockDim.x + threadIdx.x;
    if (i < n) {
        int rp = g_rowptr[i] + g_bsum[i >> 10];
        g_rowptr[i] = rp;
        g_cur[i]    = rp;
    }
    if (i == 0) g_rowptr[n] = e;
}

__global__ void fill_kernel(const int* __restrict__ src, const int* __restrict__ dst, int e) {
    int i = blockIdx.x * blockDim.x + threadIdx.x;
    if (i < e) {
        int s = src[i];
        int d = dst[i];
        int p = atomicAdd(&g_cur[d], 1);
        g_csr[p] = make_int2(s, __float_as_int(g_dinv[s] * g_dinv[d]));
    }
}

// ---------------------------------------------------------------------------
// Weight conversion kernels (tiny)
// ---------------------------------------------------------------------------
__global__ void w1cvt_kernel(const float* __restrict__ w1) {
    int i = blockIdx.x * blockDim.x + threadIdx.x;   // 256*512
    if (i >= 256 * 512) return;
    int n = i >> 9;
    int k = i & 511;
    float v = (k < F_IN) ? w1[(size_t)k * F_HID + n] : 0.f;
    g_w1b[n * 512 + k] = __float2bfloat16(v);
}

__global__ void w2cvt_kernel(const float* __restrict__ w2) {
    int i = blockIdx.x * blockDim.x + threadIdx.x;   // 40*256
    if (i >= 40 * 256) return;
    int n = i >> 8;
    int k = i & 255;
    g_w2b[n * 256 + k] = __float2bfloat16(w2[(size_t)k * F_OUT + n]);
}

// ---------------------------------------------------------------------------
// mma / cp.async helpers
// ---------------------------------------------------------------------------
__device__ __forceinline__ void mma_bf16(float c[4],
                                         const uint32_t a[4],
                                         const uint32_t b[2]) {
    asm volatile(
        "mma.sync.aligned.m16n8k16.row.col.f32.bf16.bf16.f32 "
        "{%0,%1,%2,%3}, {%4,%5,%6,%7}, {%8,%9}, {%0,%1,%2,%3};"
        : "+f"(c[0]), "+f"(c[1]), "+f"(c[2]), "+f"(c[3])
        : "r"(a[0]), "r"(a[1]), "r"(a[2]), "r"(a[3]), "r"(b[0]), "r"(b[1]));
}

__device__ __forceinline__ void cp_async16(uint32_t dst_smem, const void* src) {
    asm volatile("cp.async.cg.shared.global [%0], [%1], 16;\n"
                 :: "r"(dst_smem), "l"(src));
}
__device__ __forceinline__ void cp_commit() {
    asm volatile("cp.async.commit_group;\n");
}

struct alignas(8) bf16x4 { __nv_bfloat162 a, b; };

// ---------------------------------------------------------------------------
// GEMM1 (bf16 tensor cores): h1 = relu(x @ w1 + b1)  [M,500]x[500,256]
// Block tile 128x256x32 (full N -> x read once). 512 threads, 16 warps
// arranged 4(M)x4(N), warp tile 32x64. bf16 m16n8k16, fp32 accumulate.
// A staged LDG.128 -> cvt -> STS; B (w1^T bf16) staged via cp.async.
// 2-stage double buffer.
// ---------------------------------------------------------------------------
#define G1_AH 5120            // halfs per A stage: 128*40
#define G1_BH 10240           // halfs per B stage: 256*40
#define G1_SMEM ((2*(G1_AH + G1_BH)) * 2)   // 61440 bytes
#define G1_NT 16              // ceil(500/32)

__global__ void __launch_bounds__(512, 1)
gemm1_tc_kernel(const float* __restrict__ A, const float* __restrict__ bias, int M) {
    extern __shared__ __align__(16) __nv_bfloat16 sm[];
    // layout: [2][128][40] A halfs, then [2][256][40] B halfs

    int tid  = threadIdx.x;
    int warp = tid >> 5;
    int lane = tid & 31;
    int g = lane >> 2;    // 0..7
    int t = lane & 3;     // 0..3
    int wm = warp >> 2;   // 0..3 : rows wm*32
    int wn = warp & 3;    // 0..3 : cols wn*64
    int row0 = blockIdx.x * 128;

    uint32_t smem_u = (uint32_t)__cvta_generic_to_shared(sm);

    float c[2][8][4];
    #pragma unroll
    for (int i = 0; i < 2; i++)
        #pragma unroll
        for (int j = 0; j < 8; j++)
            #pragma unroll
            for (int q = 0; q < 4; q++) c[i][j][q] = 0.f;

    auto stage = [&](int tt, int p) {
        int kt = tt * 32;
        __nv_bfloat16* Ab = sm + p * G1_AH;
        // A: 128x32 fp32 -> bf16. 1024 float4 over 512 threads, 2 iters.
        #pragma unroll
        for (int i = 0; i < 2; i++) {
            int id = tid + i * 512;
            int r  = id >> 3;
            int c4 = id & 7;
            int gr = row0 + r;
            int gk = kt + c4 * 4;
            float4 v = make_float4(0.f, 0.f, 0.f, 0.f);
            if (gr < M && gk < F_IN)
                v = *(const float4*)(A + (size_t)gr * F_IN + gk);
            bf16x4 h;
            h.a = __floats2bfloat162_rn(v.x, v.y);
            h.b = __floats2bfloat162_rn(v.z, v.w);
            *(bf16x4*)(Ab + r * 40 + c4 * 4) = h;
        }
        // B: 256x32 bf16 via cp.async (g_w1b is [n][512], zero-padded k)
        #pragma unroll
        for (int i = 0; i < 2; i++) {
            int id = tid + i * 512;
            int n  = id >> 2;
            int ch = id & 3;
            uint32_t dsth = (uint32_t)(2 * G1_AH + p * G1_BH + n * 40 + ch * 8);
            cp_async16(smem_u + dsth * 2, g_w1b + n * 512 + kt + ch * 8);
        }
        cp_commit();
    };

    stage(0, 0);

    for (int tt = 0; tt < G1_NT; ++tt) {
        if (tt + 1 < G1_NT) {
            stage(tt + 1, (tt + 1) & 1);
            asm volatile("cp.async.wait_group 1;\n");
        } else {
            asm volatile("cp.async.wait_group 0;\n");
        }
        __syncthreads();

        int p = tt & 1;
        const uint32_t* Au = (const uint32_t*)(sm + p * G1_AH);
        const uint32_t* Bu = (const uint32_t*)(sm + 2 * G1_AH + p * G1_BH);

        #pragma unroll
        for (int s = 0; s < 2; s++) {
            int kb = s * 8;   // u32 offset for k-step
            uint32_t bf[8][2];
            #pragma unroll
            for (int nt = 0; nt < 8; nt++) {
                int bn = wn * 64 + nt * 8 + g;
                bf[nt][0] = Bu[bn * 20 + t + kb];
                bf[nt][1] = Bu[bn * 20 + t + 4 + kb];
            }
            #pragma unroll
            for (int mt = 0; mt < 2; mt++) {
                int ar = wm * 32 + mt * 16 + g;
                uint32_t af[4];
                af[0] = Au[ar * 20 + t + kb];
                af[1] = Au[(ar + 8) * 20 + t + kb];
                af[2] = Au[ar * 20 + t + 4 + kb];
                af[3] = Au[(ar + 8) * 20 + t + 4 + kb];
                #pragma unroll
                for (int nt = 0; nt < 8; nt++)
                    mma_bf16(c[mt][nt], af, bf[nt]);
            }
        }
        __syncthreads();
    }

    // Epilogue: bias + relu -> g_h1b (bf16, padded rows, no guard)
    #pragma unroll
    for (int nt = 0; nt < 8; nt++) {
        int cc = wn * 64 + nt * 8 + 2 * t;
        float b0 = bias[cc], b1 = bias[cc + 1];
        #pragma unroll
        for (int mt = 0; mt < 2; mt++) {
            int r0 = row0 + wm * 32 + mt * 16 + g;
            int r1 = r0 + 8;
            *(__nv_bfloat162*)(g_h1b + (size_t)r0 * F_HID + cc) =
                __floats2bfloat162_rn(fmaxf(c[mt][nt][0] + b0, 0.f),
                                      fmaxf(c[mt][nt][1] + b1, 0.f));
            *(__nv_bfloat162*)(g_h1b + (size_t)r1 * F_HID + cc) =
                __floats2bfloat162_rn(fmaxf(c[mt][nt][2] + b0, 0.f),
                                      fmaxf(c[mt][nt][3] + b1, 0.f));
        }
    }
}

// ---------------------------------------------------------------------------
// GEMM2 (bf16 tensor cores) + init: h = h1 @ w2 + b2 ; hidden = temp[0]*h
// Block: 128 rows x full K=256 x N=40. 256 threads = 8 warps, warp = 16 rows.
// Single smem stage (A tile 128x256 bf16 + w2^T), cp.async.
// ---------------------------------------------------------------------------
#define G2_AW 264                      // halfs per A row (256+8 pad)
#define G2_AH (128 * G2_AW)            // 33792 halfs
#define G2_BH (40 * G2_AW)             // 10560 halfs
#define G2_SMEM ((G2_AH + G2_BH) * 2)  // 88704 bytes

__global__ void __launch_bounds__(256)
gemm2_tc_kernel(const float* __restrict__ b2, const float* __restrict__ temp, int M) {
    extern __shared__ __align__(16) __nv_bfloat16 sm2[];
    int tid  = threadIdx.x;
    int warp = tid >> 5;
    int lane = tid & 31;
    int g = lane >> 2;
    int t = lane & 3;
    int rbase = blockIdx.x * 128;

    uint32_t smem_u = (uint32_t)__cvta_generic_to_shared(sm2);

    // stage A: 128 rows x 256 halfs = 4096 x 16B chunks
    #pragma unroll
    for (int i = 0; i < 16; i++) {
        int id = tid + i * 256;
        int r  = id >> 5;
        int ch = id & 31;
        cp_async16(smem_u + (uint32_t)(r * G2_AW + ch * 8) * 2,
                   g_h1b + (size_t)(rbase + r) * F_HID + ch * 8);
    }
    // stage B: 40 rows x 256 halfs = 1280 chunks
    #pragma unroll
    for (int i = 0; i < 5; i++) {
        int id = tid + i * 256;
        int n  = id >> 5;
        int ch = id & 31;
        cp_async16(smem_u + (uint32_t)(G2_AH + n * G2_AW + ch * 8) * 2,
                   g_w2b + n * 256 + ch * 8);
    }
    cp_commit();
    asm volatile("cp.async.wait_group 0;\n");
    __syncthreads();

    const uint32_t* Au = (const uint32_t*)sm2;
    const uint32_t* Bu = (const uint32_t*)(sm2 + G2_AH);
    const int STR = G2_AW / 2;   // 132 u32 per row

    float c[5][4];
    #pragma unroll
    for (int j = 0; j < 5; j++)
        #pragma unroll
        for (int q = 0; q < 4; q++) c[j][q] = 0.f;

    int rw = warp * 16;
    #pragma unroll
    for (int ks = 0; ks < 16; ks++) {
        int kb = ks * 8;
        uint32_t af[4];
        af[0] = Au[(rw + g) * STR + t + kb];
        af[1] = Au[(rw + g + 8) * STR + t + kb];
        af[2] = Au[(rw + g) * STR + t + 4 + kb];
        af[3] = Au[(rw + g + 8) * STR + t + 4 + kb];
        #pragma unroll
        for (int nt = 0; nt < 5; nt++) {
            uint32_t bfr[2];
            int bn = nt * 8 + g;
            bfr[0] = Bu[bn * STR + t + kb];
            bfr[1] = Bu[bn * STR + t + 4 + kb];
            mma_bf16(c[nt], af, bfr);
        }
    }

    float t0 = temp[0];
    #pragma unroll
    for (int nt = 0; nt < 5; nt++) {
        int cc = nt * 8 + 2 * t;
        float b0 = b2[cc], b1 = b2[cc + 1];
        int r0 = rbase + rw + g;
        int r1 = r0 + 8;
        float v00 = c[nt][0] + b0, v01 = c[nt][1] + b1;
        float v10 = c[nt][2] + b0, v11 = c[nt][3] + b1;
        g_ha[(size_t)r0 * F_PAD + cc]     = v00;
        g_ha[(size_t)r0 * F_PAD + cc + 1] = v01;
        g_ha[(size_t)r1 * F_PAD + cc]     = v10;
        g_ha[(size_t)r1 * F_PAD + cc + 1] = v11;
        g_hidden[(size_t)r0 * F_OUT + cc]     = t0 * v00;
        g_hidden[(size_t)r0 * F_OUT + cc + 1] = t0 * v01;
        g_hidden[(size_t)r1 * F_OUT + cc]     = t0 * v10;
        g_hidden[(size_t)r1 * F_OUT + cc + 1] = t0 * v11;
    }
}

// ---------------------------------------------------------------------------
// Propagation: warp per dst node, lane l owns features l and 32+l (<40).
// Feature rows padded to 64 floats (256B) -> line-aligned gathers.
// ---------------------------------------------------------------------------
__device__ __forceinline__ void prop_accum(int node, const float* __restrict__ hin,
                                           int lane, float& acc0, float& acc1) {
    int beg = g_rowptr[node];
    int end = g_rowptr[node + 1];

    float dv = g_dinv[node];
    float wself = dv * dv;

    const float* rin = hin + (size_t)node * F_PAD;
    acc0 = wself * rin[lane];
    acc1 = (lane < 8) ? wself * rin[32 + lane] : 0.f;

    for (int e = beg; e < end; e += 32) {
        int idx = e + lane;
        int2 ev = make_int2(0, 0);
        if (idx < end) ev = g_csr[idx];
        int cnt = min(32, end - e);
        #pragma unroll 8
        for (int j = 0; j < cnt; ++j) {
            int   sj = __shfl_sync(0xffffffffu, ev.x, j);
            float wj = __int_as_float(__shfl_sync(0xffffffffu, ev.y, j));
            const float* rs = hin + (size_t)sj * F_PAD;
            acc0 += wj * rs[lane];
            if (lane < 8) acc1 += wj * rs[32 + lane];
        }
    }
}

__global__ void __launch_bounds__(256)
prop_step_kernel(const float* __restrict__ temp, int n, int k, int odd) {
    int warp = (blockIdx.x * blockDim.x + threadIdx.x) >> 5;
    int lane = threadIdx.x & 31;
    if (warp >= n) return;

    const float* __restrict__ hin = odd ? g_ha : g_hb;
    float* __restrict__ hout      = odd ? g_hb : g_ha;

    float acc0, acc1;
    prop_accum(warp, hin, lane, acc0, acc1);

    float gamma = temp[k];
    size_t op = (size_t)warp * F_PAD;
    size_t oh = (size_t)warp * F_OUT;
    hout[op + lane] = acc0;
    g_hidden[oh + lane] += gamma * acc0;
    if (lane < 8) {
        hout[op + 32 + lane] = acc1;
        g_hidden[oh + 32 + lane] += gamma * acc1;
    }
}

// Final step (k = K_STEPS, hin = g_hb) fused with log_softmax -> out.
__global__ void __launch_bounds__(256)
prop_last_kernel(const float* __restrict__ temp, int n, float* __restrict__ out) {
    int warp = (blockIdx.x * blockDim.x + threadIdx.x) >> 5;
    int lane = threadIdx.x & 31;
    if (warp >= n) return;

    float acc0, acc1;
    prop_accum(warp, g_hb, lane, acc0, acc1);

    float gamma = temp[K_STEPS];
    size_t oh = (size_t)warp * F_OUT;
    float v0 = g_hidden[oh + lane] + gamma * acc0;
    float v1 = (lane < 8) ? (g_hidden[oh + 32 + lane] + gamma * acc1) : -INFINITY;

    float m = fmaxf(v0, v1);
    #pragma unroll
    for (int off = 16; off; off >>= 1)
        m = fmaxf(m, __shfl_xor_sync(0xffffffffu, m, off));

    float s = expf(v0 - m) + ((lane < 8) ? expf(v1 - m) : 0.f);
    #pragma unroll
    for (int off = 16; off; off >>= 1)
        s += __shfl_xor_sync(0xffffffffu, s, off);

    float ls = logf(s);
    out[oh + lane] = v0 - m - ls;
    if (lane < 8) out[oh + 32 + lane] = v1 - m - ls;
}

// ---------------------------------------------------------------------------
// Launch
// ---------------------------------------------------------------------------
extern "C" void kernel_launch(void* const* d_in, const int* in_sizes, int n_in,
                              void* d_out, int out_size) {
    const float* x    = (const float*)d_in[0];
    const int*   ei   = (const int*)  d_in[1];
    const float* w1   = (const float*)d_in[2];
    const float* b1   = (const float*)d_in[3];
    const float* w2   = (const float*)d_in[4];
    const float* b2   = (const float*)d_in[5];
    const float* temp = (const float*)d_in[6];
    float* out = (float*)d_out;

    int N = in_sizes[0] / F_IN;   // 100000
    int E = in_sizes[1] / 2;      // 1600000
    const int* src = ei;
    const int* dst = ei + E;

    // CSR build
    void* count_ptr = nullptr;
    cudaGetSymbolAddress(&count_ptr, g_count);
    cudaMemsetAsync(count_ptr, 0, (size_t)N * sizeof(int));
    count_kernel<<<(E + 255) / 256, 256>>>(dst, E);
    int nb = (N + 1023) / 1024;
    scan1_kernel<<<nb, 1024>>>(N);
    scan2_kernel<<<1, 128>>>(nb);
    scan3_kernel<<<(N + 255) / 256, 256>>>(N, E);
    fill_kernel<<<(E + 255) / 256, 256>>>(src, dst, E);

    // Weight prep
    w1cvt_kernel<<<(256 * 512 + 255) / 256, 256>>>(w1);
    w2cvt_kernel<<<(40 * 256 + 255) / 256, 256>>>(w2);

    // MLP on tensor cores (attributes set unconditionally — no static guards)
    cudaFuncSetAttribute(gemm1_tc_kernel,
                         cudaFuncAttributeMaxDynamicSharedMemorySize, G1_SMEM);
    cudaFuncSetAttribute(gemm2_tc_kernel,
                         cudaFuncAttributeMaxDynamicSharedMemorySize, G2_SMEM);
    int mblocks = (N + 127) / 128;   // 782
    gemm1_tc_kernel<<<mblocks, 512, G1_SMEM>>>(x, b1, N);
    gemm2_tc_kernel<<<mblocks, 256, G2_SMEM>>>(b2, temp, N);

    // APPNP-style propagation (last step fused with log_softmax)
    int warp_blocks = (N * 32 + 255) / 256;
    for (int k = 1; k < K_STEPS; ++k)
        prop_step_kernel<<<warp_blocks, 256>>>(temp, N, k, k & 1);
    prop_last_kernel<<<warp_blocks, 256>>>(temp, N, out);
}